// round 16
// baseline (speedup 1.0000x reference)
#include <cuda_runtime.h>
#include <cuda_fp16.h>

#define N_NODES 100000
#define F_IN    64
#define H_DIM   32
#define C_DIM   5
#define BSTRIDE 96                               // max bucket capacity (Poisson(32) tail-safe)

// ---- scratch (device globals; no allocation allowed) ----
// g_cd is zero at module load; prep re-zeros it each run (graph-replay safe).
__device__ unsigned long long g_cd[N_NODES];     // packed: count<<40 | qsum(w * 2^24)
__device__ float g_dinv[N_NODES];
__device__ int   g_cnt [N_NODES];
__device__ int2  g_edge[N_NODES * BSTRIDE];      // {src, w-as-bits}, fixed-stride buckets
__device__ float g_h  [N_NODES * H_DIM];         // x @ W1 (fp32, unscaled)
__device__ __half g_hh[N_NODES * H_DIM];         // (x @ W1) * dinv, fp16 64B rows
__device__ __align__(16) __half g_h2h[N_NODES * 8];  // (x1 @ W2) * dinv, fp16 16B rows

// ---------------- stage 1: fat kernel — hist (packed atomic + direct bucket write) + gemm1 ----------------

__global__ void k_hist_gemm1(const int* __restrict__ src, const int* __restrict__ dst,
                             const float* __restrict__ w, int E,
                             const float* __restrict__ x, const float* __restrict__ W1,
                             int gemmBlocks, int histThreads) {
    if ((int)blockIdx.x < gemmBlocks) {
        // ---- gemm1: g_h = x @ W1 (unscaled), 2 threads/node, 16 outputs each ----
        __shared__ float4 Ws[F_IN * H_DIM / 4];
        for (int i = threadIdx.x; i < F_IN * H_DIM / 4; i += blockDim.x)
            Ws[i] = ((const float4*)W1)[i];
        __syncthreads();

        int t = blockIdx.x * blockDim.x + threadIdx.x;
        int node = t >> 1;
        if (node >= N_NODES) return;
        int half = t & 1;
        int jb = half * 4;

        const float4* xr = (const float4*)(x + (size_t)node * F_IN);
        float acc[16];
#pragma unroll
        for (int j = 0; j < 16; j++) acc[j] = 0.f;

#pragma unroll
        for (int k4 = 0; k4 < F_IN / 4; k4++) {
            float4 xv = xr[k4];
#pragma unroll
            for (int r = 0; r < 4; r++) {
                int k = k4 * 4 + r;
                float xs = (r == 0) ? xv.x : (r == 1) ? xv.y : (r == 2) ? xv.z : xv.w;
#pragma unroll
                for (int j4 = 0; j4 < 4; j4++) {
                    float4 wv = Ws[k * 8 + jb + j4];
                    acc[j4 * 4 + 0] += xs * wv.x;
                    acc[j4 * 4 + 1] += xs * wv.y;
                    acc[j4 * 4 + 2] += xs * wv.z;
                    acc[j4 * 4 + 3] += xs * wv.w;
                }
            }
        }
        float4* hp = (float4*)(g_h + (size_t)node * H_DIM + half * 16);
#pragma unroll
        for (int j4 = 0; j4 < 4; j4++)
            hp[j4] = make_float4(acc[j4 * 4 + 0], acc[j4 * 4 + 1],
                                 acc[j4 * 4 + 2], acc[j4 * 4 + 3]);
    } else {
        // ---- hist: 4 edges/thread grid-strided (coalesced per round, 4 atomic chains) ----
        int i = (blockIdx.x - gemmBlocks) * blockDim.x + threadIdx.x;
#pragma unroll
        for (int q = 0; q < 4; q++) {
            int e = i + q * histThreads;
            if (e < E) {
                int d = dst[e];
                float wv = w[e];
                unsigned long long qw = (unsigned long long)__float2uint_rn(wv * 16777216.0f);
                unsigned long long old = atomicAdd(&g_cd[d], (1ull << 40) | qw);
                int rank = (int)(old >> 40);
                if (rank < BSTRIDE)
                    g_edge[(size_t)d * BSTRIDE + rank] = make_int2(src[e], __float_as_int(wv));
            }
        }
    }
}

// ---------------- stage 2: prep — g_hh = fp16(g_h * dinv), emit dinv + cnt, reset g_cd ----------------

__global__ void k_prep() {
    const unsigned long long QMASK = (1ull << 40) - 1ull;
    const float QS = 5.9604644775390625e-8f;   // 2^-24

    int i = blockIdx.x * blockDim.x + threadIdx.x;   // over N * 8 float4s
    if (i >= N_NODES * (H_DIM / 4)) return;
    int node = i >> 3;
    unsigned long long v = g_cd[node];
    float deg = 1.0f + (float)(v & QMASK) * QS;      // self-loop + sum(w)
    float dv = rsqrtf(deg);
    float4 h = ((float4*)g_h)[i];
    __half2 lo = __floats2half2_rn(h.x * dv, h.y * dv);
    __half2 hi = __floats2half2_rn(h.z * dv, h.w * dv);
    uint2 pk;
    pk.x = *(unsigned*)&lo;
    pk.y = *(unsigned*)&hi;
    *(uint2*)(g_hh + 4 * (size_t)i) = pk;
    if ((i & 7) == 0) {
        g_dinv[node] = dv;
        int c = (int)(v >> 40);
        g_cnt[node] = c < BSTRIDE ? c : BSTRIDE;
        g_cd[node] = 0ull;    // reset for next graph replay (hist runs after this)
    }
}

// ---------------- stage 3: agg1 pull — HALF-WARP per node + fused gemm2 ----------------

__global__ void k_agg1(const float* __restrict__ b1, const float* __restrict__ W2,
                       float* __restrict__ x1out) {
    int node = (blockIdx.x * blockDim.x + threadIdx.x) >> 4;   // half-warp index
    if (node >= N_NODES) return;
    int f2 = threadIdx.x & 15;
    int hbase = threadIdx.x & 16;               // 0 or 16
    unsigned hmask = 0xFFFFu << hbase;          // this half's lanes only
    int beg = node * BSTRIDE;
    int end = beg + g_cnt[node];

    // self loop (all 16 lanes of the half)
    __half2 sh = *(const __half2*)(g_hh + (size_t)node * H_DIM + 2 * f2);
    float2 sf = __half22float2(sh);
    float accx = sf.x, accy = sf.y;

    for (int e = beg; e < end; e += 16) {
        int idx = e + f2;
        int   sE = 0;
        float wE = 0.f;
        if (idx < end) {
            int2 ed = g_edge[idx];
            sE = ed.x; wE = __int_as_float(ed.y);
        }
        int nn = end - e; if (nn > 16) nn = 16;
        {
            int   s0[8];
            float w0[8];
            __half2 v0[8];
#pragma unroll
            for (int j = 0; j < 8; j++) {
                s0[j] = __shfl_sync(hmask, sE, hbase + j);
                w0[j] = __shfl_sync(hmask, wE, hbase + j);
            }
#pragma unroll
            for (int j = 0; j < 8; j++)
                v0[j] = *(const __half2*)(g_hh + (size_t)s0[j] * H_DIM + 2 * f2);
#pragma unroll
            for (int j = 0; j < 8; j++) {
                float2 f = __half22float2(v0[j]);
                accx += w0[j] * f.x;
                accy += w0[j] * f.y;
            }
        }
        if (nn > 8) {
            int   s0[8];
            float w0[8];
            __half2 v0[8];
#pragma unroll
            for (int j = 0; j < 8; j++) {
                s0[j] = __shfl_sync(hmask, sE, hbase + 8 + j);
                w0[j] = __shfl_sync(hmask, wE, hbase + 8 + j);
            }
#pragma unroll
            for (int j = 0; j < 8; j++)
                v0[j] = *(const __half2*)(g_hh + (size_t)s0[j] * H_DIM + 2 * f2);
#pragma unroll
            for (int j = 0; j < 8; j++) {
                float2 f = __half22float2(v0[j]);
                accx += w0[j] * f.x;
                accy += w0[j] * f.y;
            }
        }
    }

    float dv = g_dinv[node];
    float v0f = accx * dv + b1[2 * f2];
    float v1f = accy * dv + b1[2 * f2 + 1];
    v0f = v0f > 0.f ? v0f : 0.f;
    v1f = v1f > 0.f ? v1f : 0.f;
    *(float2*)(x1out + (size_t)node * H_DIM + 2 * f2) = make_float2(v0f, v1f);

    // fused gemm2: fold over the 16 lanes of this half
    float p0 = v0f * W2[(2 * f2) * C_DIM + 0] + v1f * W2[(2 * f2 + 1) * C_DIM + 0];
    float p1 = v0f * W2[(2 * f2) * C_DIM + 1] + v1f * W2[(2 * f2 + 1) * C_DIM + 1];
    float p2 = v0f * W2[(2 * f2) * C_DIM + 2] + v1f * W2[(2 * f2 + 1) * C_DIM + 2];
    float p3 = v0f * W2[(2 * f2) * C_DIM + 3] + v1f * W2[(2 * f2 + 1) * C_DIM + 3];
    float p4 = v0f * W2[(2 * f2) * C_DIM + 4] + v1f * W2[(2 * f2 + 1) * C_DIM + 4];
#pragma unroll
    for (int o = 8; o > 0; o >>= 1) {
        p0 += __shfl_xor_sync(hmask, p0, o);
        p1 += __shfl_xor_sync(hmask, p1, o);
        p2 += __shfl_xor_sync(hmask, p2, o);
        p3 += __shfl_xor_sync(hmask, p3, o);
        p4 += __shfl_xor_sync(hmask, p4, o);
    }
    if (f2 == 0) {
        __half2 q0 = __floats2half2_rn(p0 * dv, p1 * dv);
        __half2 q1 = __floats2half2_rn(p2 * dv, p3 * dv);
        __half2 q2 = __floats2half2_rn(p4 * dv, 0.f);
        uint4 pk;
        pk.x = *(unsigned*)&q0;
        pk.y = *(unsigned*)&q1;
        pk.z = *(unsigned*)&q2;
        pk.w = 0u;
        *(uint4*)(g_h2h + (size_t)node * 8) = pk;
    }
}

// ---------------- stage 4: agg2 pull — QUARTER-WARP per node, lane8 = edge ----------------

__global__ void k_agg2(const float* __restrict__ b2, float* __restrict__ out) {
    int node = (blockIdx.x * blockDim.x + threadIdx.x) >> 3;   // quarter-warp index
    if (node >= N_NODES) return;
    int l8 = threadIdx.x & 7;
    int qbase = threadIdx.x & 24;               // 0/8/16/24
    unsigned qmask = 0xFFu << qbase;
    int beg = node * BSTRIDE;
    int n = g_cnt[node];

    float a0 = 0.f, a1 = 0.f, a2 = 0.f, a3 = 0.f, a4 = 0.f;
    if (l8 == 0) {   // self loop: own fp16 row
        uint4 r = *(const uint4*)(g_h2h + (size_t)node * 8);
        float2 f01 = __half22float2(*(__half2*)&r.x);
        float2 f23 = __half22float2(*(__half2*)&r.y);
        float2 f4x = __half22float2(*(__half2*)&r.z);
        a0 = f01.x; a1 = f01.y; a2 = f23.x; a3 = f23.y; a4 = f4x.x;
    }

    if (n > 0) {
        int nm1 = n - 1;
        // straight-line 4 clamped rounds (covers n <= 32, the common case)
        int2 er[4];
        uint4 rr[4];
        float wr[4];
#pragma unroll
        for (int q = 0; q < 4; q++) {
            int pos = l8 + q * 8;
            int ic = pos < nm1 ? pos : nm1;
            er[q] = g_edge[beg + ic];
        }
#pragma unroll
        for (int q = 0; q < 4; q++)
            rr[q] = *(const uint4*)(g_h2h + (size_t)er[q].x * 8);
#pragma unroll
        for (int q = 0; q < 4; q++)
            wr[q] = (l8 + q * 8 < n) ? __int_as_float(er[q].y) : 0.f;
#pragma unroll
        for (int q = 0; q < 4; q++) {
            float2 f01 = __half22float2(*(__half2*)&rr[q].x);
            float2 f23 = __half22float2(*(__half2*)&rr[q].y);
            float2 f4x = __half22float2(*(__half2*)&rr[q].z);
            a0 += wr[q] * f01.x; a1 += wr[q] * f01.y;
            a2 += wr[q] * f23.x; a3 += wr[q] * f23.y;
            a4 += wr[q] * f4x.x;
        }
        // loop for n > 32
        for (int e = beg + 32 + l8; e < beg + n; e += 8) {
            int2 et = g_edge[e];
            uint4 rt = *(const uint4*)(g_h2h + (size_t)et.x * 8);
            float wt = __int_as_float(et.y);
            float2 h01 = __half22float2(*(__half2*)&rt.x);
            float2 h23 = __half22float2(*(__half2*)&rt.y);
            float2 h4x = __half22float2(*(__half2*)&rt.z);
            a0 += wt * h01.x; a1 += wt * h01.y;
            a2 += wt * h23.x; a3 += wt * h23.y;
            a4 += wt * h4x.x;
        }
    }

    // fold within the 8-lane quarter
#pragma unroll
    for (int o = 4; o > 0; o >>= 1) {
        a0 += __shfl_xor_sync(qmask, a0, o);
        a1 += __shfl_xor_sync(qmask, a1, o);
        a2 += __shfl_xor_sync(qmask, a2, o);
        a3 += __shfl_xor_sync(qmask, a3, o);
        a4 += __shfl_xor_sync(qmask, a4, o);
    }
    if (l8 < C_DIM) {
        float val = (l8 == 0) ? a0 : (l8 == 1) ? a1 : (l8 == 2) ? a2 :
                    (l8 == 3) ? a3 : a4;
        out[(size_t)node * C_DIM + l8] = val * g_dinv[node] + b2[l8];
    }
}

// ---------------- launch ----------------

extern "C" void kernel_launch(void* const* d_in, const int* in_sizes, int n_in,
                              void* d_out, int out_size) {
    const float* x   = (const float*)d_in[0];
    const int*   ei  = (const int*)d_in[1];     // JAX demotes int64 -> int32
    const float* ew  = (const float*)d_in[2];
    const float* W1  = (const float*)d_in[3];
    const float* b1  = (const float*)d_in[4];
    const float* W2  = (const float*)d_in[5];
    const float* b2  = (const float*)d_in[6];
    float* out = (float*)d_out;

    const int E = in_sizes[2];
    const int* src = ei;
    const int* dst = ei + E;

    float* x2_out = out;                            // [N, C]
    float* x1_out = out + (size_t)N_NODES * C_DIM;  // [N, H]

    const int T = 256;
    const int gE4 = ((E + 3) / 4 + T - 1) / T;                  // hist: 4 edges/thread
    const int histThreads = gE4 * T;
    const int gN2 = (N_NODES * 2 + T - 1) / T;                  // gemm1 blocks
    const int gP  = (N_NODES * (H_DIM / 4) + T - 1) / T;        // prep blocks
    const int gH  = (N_NODES * 16 + T - 1) / T;                 // half-warp/node (agg1)
    const int gQ  = (N_NODES * 8 + T - 1) / T;                  // quarter-warp/node (agg2)

    k_hist_gemm1 <<<gN2 + gE4, T>>>(src, dst, ew, E, x, W1, gN2, histThreads);
    k_prep       <<<gP,        T>>>();
    k_agg1       <<<gH,        T>>>(b1, W2, x1_out);
    k_agg2       <<<gQ,        T>>>(b2, x2_out);
}

// round 17
// speedup vs baseline: 1.0453x; 1.0453x over previous
#include <cuda_runtime.h>
#include <cuda_fp16.h>

#define N_NODES 100000
#define F_IN    64
#define H_DIM   32
#define C_DIM   5
#define BSTRIDE 96                               // max bucket capacity (Poisson(32) tail-safe)

// ---- scratch (device globals; no allocation allowed) ----
// g_cd is zero at module load; prep re-zeros it each run (graph-replay safe).
__device__ unsigned long long g_cd[N_NODES];     // packed: count<<40 | qsum(w * 2^24)
__device__ float g_dinv[N_NODES];
__device__ int   g_cnt [N_NODES];
__device__ int2  g_edge[N_NODES * BSTRIDE];      // {src, w-as-bits}, fixed-stride buckets
__device__ float g_h  [N_NODES * H_DIM];         // x @ W1 (fp32, unscaled)
__device__ __half g_hh[N_NODES * H_DIM];         // (x @ W1) * dinv, fp16 64B rows
__device__ __align__(16) __half g_h2h[N_NODES * 8];  // (x1 @ W2) * dinv, fp16 16B rows

// ---------------- stage 1: fat kernel — hist (packed atomic + direct bucket write) + gemm1 ----------------

__global__ void k_hist_gemm1(const int* __restrict__ src, const int* __restrict__ dst,
                             const float* __restrict__ w, int E,
                             const float* __restrict__ x, const float* __restrict__ W1,
                             int gemmBlocks) {
    if ((int)blockIdx.x < gemmBlocks) {
        // ---- gemm1: g_h = x @ W1 (unscaled), 2 threads/node, 16 outputs each ----
        __shared__ float4 Ws[F_IN * H_DIM / 4];
        for (int i = threadIdx.x; i < F_IN * H_DIM / 4; i += blockDim.x)
            Ws[i] = ((const float4*)W1)[i];
        __syncthreads();

        int t = blockIdx.x * blockDim.x + threadIdx.x;
        int node = t >> 1;
        if (node >= N_NODES) return;
        int half = t & 1;
        int jb = half * 4;

        const float4* xr = (const float4*)(x + (size_t)node * F_IN);
        float acc[16];
#pragma unroll
        for (int j = 0; j < 16; j++) acc[j] = 0.f;

#pragma unroll
        for (int k4 = 0; k4 < F_IN / 4; k4++) {
            float4 xv = xr[k4];
#pragma unroll
            for (int r = 0; r < 4; r++) {
                int k = k4 * 4 + r;
                float xs = (r == 0) ? xv.x : (r == 1) ? xv.y : (r == 2) ? xv.z : xv.w;
#pragma unroll
                for (int j4 = 0; j4 < 4; j4++) {
                    float4 wv = Ws[k * 8 + jb + j4];
                    acc[j4 * 4 + 0] += xs * wv.x;
                    acc[j4 * 4 + 1] += xs * wv.y;
                    acc[j4 * 4 + 2] += xs * wv.z;
                    acc[j4 * 4 + 3] += xs * wv.w;
                }
            }
        }
        float4* hp = (float4*)(g_h + (size_t)node * H_DIM + half * 16);
#pragma unroll
        for (int j4 = 0; j4 < 4; j4++)
            hp[j4] = make_float4(acc[j4 * 4 + 0], acc[j4 * 4 + 1],
                                 acc[j4 * 4 + 2], acc[j4 * 4 + 3]);
    } else {
        // ---- hist: 2 edges/thread; packed atomic gives rank+count+qdeg; direct bucket write ----
        int i = (blockIdx.x - gemmBlocks) * blockDim.x + threadIdx.x;
        int e0 = 2 * i;
        if (e0 >= E) return;
#pragma unroll
        for (int q = 0; q < 2; q++) {
            int e = e0 + q;
            if (e >= E) break;
            int d = dst[e];
            float wv = w[e];
            unsigned long long qw = (unsigned long long)__float2uint_rn(wv * 16777216.0f);
            unsigned long long old = atomicAdd(&g_cd[d], (1ull << 40) | qw);
            int rank = (int)(old >> 40);
            if (rank < BSTRIDE)
                g_edge[(size_t)d * BSTRIDE + rank] = make_int2(src[e], __float_as_int(wv));
        }
    }
}

// ---------------- stage 2: prep — g_hh = fp16(g_h * dinv), zero-pad bucket tails ----------------

__global__ void k_prep() {
    const unsigned long long QMASK = (1ull << 40) - 1ull;
    const float QS = 5.9604644775390625e-8f;   // 2^-24

    int i = blockIdx.x * blockDim.x + threadIdx.x;   // over N * 8 float4s
    if (i >= N_NODES * (H_DIM / 4)) return;
    int node = i >> 3;
    int sub = i & 7;
    unsigned long long v = g_cd[node];
    float deg = 1.0f + (float)(v & QMASK) * QS;      // self-loop + sum(w)
    float dv = rsqrtf(deg);
    float4 h = ((float4*)g_h)[i];
    __half2 lo = __floats2half2_rn(h.x * dv, h.y * dv);
    __half2 hi = __floats2half2_rn(h.z * dv, h.w * dv);
    uint2 pk;
    pk.x = *(unsigned*)&lo;
    pk.y = *(unsigned*)&hi;
    *(uint2*)(g_hh + 4 * (size_t)i) = pk;

    int c = (int)(v >> 40);
    c = c < BSTRIDE ? c : BSTRIDE;
    if (sub == 0) {
        g_dinv[node] = dv;
        g_cnt[node] = c;
        g_cd[node] = 0ull;    // reset for next graph replay (hist runs after this)
    }
    // zero-pad bucket tail to max(32, roundup8(cnt)) — makes agg loops branch-free
    int padTarget = (c + 7) & ~7;
    if (padTarget < 32) padTarget = 32;
    for (int p = c + sub; p < padTarget; p += 8)
        g_edge[(size_t)node * BSTRIDE + p] = make_int2(0, 0);
}

// ---------------- stage 3: agg1 pull — HALF-WARP per node, uniform edge loads + fused gemm2 ----------------

__global__ void k_agg1(const float* __restrict__ b1, const float* __restrict__ W2,
                       float* __restrict__ x1out) {
    int node = (blockIdx.x * blockDim.x + threadIdx.x) >> 4;   // half-warp index
    if (node >= N_NODES) return;
    int f2 = threadIdx.x & 15;
    int hbase = threadIdx.x & 16;               // 0 or 16
    unsigned hmask = 0xFFFFu << hbase;          // this half's lanes only
    int beg = node * BSTRIDE;
    int padEnd = beg + ((g_cnt[node] + 7) & ~7);   // zero-padded region

    // self loop (all 16 lanes of the half)
    __half2 sh = *(const __half2*)(g_hh + (size_t)node * H_DIM + 2 * f2);
    float2 sf = __half22float2(sh);
    float accx = sf.x, accy = sf.y;

    for (int e = beg; e < padEnd; e += 8) {
        int2 ed[8];
#pragma unroll
        for (int j = 0; j < 8; j++)
            ed[j] = g_edge[e + j];              // uniform across the 16 lanes (broadcast)
        __half2 v0[8];
#pragma unroll
        for (int j = 0; j < 8; j++)
            v0[j] = *(const __half2*)(g_hh + (size_t)ed[j].x * H_DIM + 2 * f2);
#pragma unroll
        for (int j = 0; j < 8; j++) {
            float2 f = __half22float2(v0[j]);
            float wv = __int_as_float(ed[j].y); // 0 in pad region
            accx += wv * f.x;
            accy += wv * f.y;
        }
    }

    float dv = g_dinv[node];
    float v0f = accx * dv + b1[2 * f2];
    float v1f = accy * dv + b1[2 * f2 + 1];
    v0f = v0f > 0.f ? v0f : 0.f;
    v1f = v1f > 0.f ? v1f : 0.f;
    *(float2*)(x1out + (size_t)node * H_DIM + 2 * f2) = make_float2(v0f, v1f);

    // fused gemm2: fold over the 16 lanes of this half
    float p0 = v0f * W2[(2 * f2) * C_DIM + 0] + v1f * W2[(2 * f2 + 1) * C_DIM + 0];
    float p1 = v0f * W2[(2 * f2) * C_DIM + 1] + v1f * W2[(2 * f2 + 1) * C_DIM + 1];
    float p2 = v0f * W2[(2 * f2) * C_DIM + 2] + v1f * W2[(2 * f2 + 1) * C_DIM + 2];
    float p3 = v0f * W2[(2 * f2) * C_DIM + 3] + v1f * W2[(2 * f2 + 1) * C_DIM + 3];
    float p4 = v0f * W2[(2 * f2) * C_DIM + 4] + v1f * W2[(2 * f2 + 1) * C_DIM + 4];
#pragma unroll
    for (int o = 8; o > 0; o >>= 1) {
        p0 += __shfl_xor_sync(hmask, p0, o);
        p1 += __shfl_xor_sync(hmask, p1, o);
        p2 += __shfl_xor_sync(hmask, p2, o);
        p3 += __shfl_xor_sync(hmask, p3, o);
        p4 += __shfl_xor_sync(hmask, p4, o);
    }
    if (f2 == 0) {
        __half2 q0 = __floats2half2_rn(p0 * dv, p1 * dv);
        __half2 q1 = __floats2half2_rn(p2 * dv, p3 * dv);
        __half2 q2 = __floats2half2_rn(p4 * dv, 0.f);
        uint4 pk;
        pk.x = *(unsigned*)&q0;
        pk.y = *(unsigned*)&q1;
        pk.z = *(unsigned*)&q2;
        pk.w = 0u;
        *(uint4*)(g_h2h + (size_t)node * 8) = pk;
    }
}

// ---------------- stage 4: agg2 pull — QUARTER-WARP per node, branch-free via padding ----------------

__global__ void k_agg2(const float* __restrict__ b2, float* __restrict__ out) {
    int node = (blockIdx.x * blockDim.x + threadIdx.x) >> 3;   // quarter-warp index
    if (node >= N_NODES) return;
    int l8 = threadIdx.x & 7;
    int qbase = threadIdx.x & 24;               // 0/8/16/24
    unsigned qmask = 0xFFu << qbase;
    int beg = node * BSTRIDE;
    int n = g_cnt[node];

    float a0 = 0.f, a1 = 0.f, a2 = 0.f, a3 = 0.f, a4 = 0.f;
    if (l8 == 0) {   // self loop: own fp16 row
        uint4 r = *(const uint4*)(g_h2h + (size_t)node * 8);
        float2 f01 = __half22float2(*(__half2*)&r.x);
        float2 f23 = __half22float2(*(__half2*)&r.y);
        float2 f4x = __half22float2(*(__half2*)&r.z);
        a0 = f01.x; a1 = f01.y; a2 = f23.x; a3 = f23.y; a4 = f4x.x;
    }

    // straight-line 4 rounds: indices 0..31 are all valid-or-zero (padded)
    {
        int2 er[4];
        uint4 rr[4];
#pragma unroll
        for (int q = 0; q < 4; q++)
            er[q] = g_edge[beg + l8 + q * 8];
#pragma unroll
        for (int q = 0; q < 4; q++)
            rr[q] = *(const uint4*)(g_h2h + (size_t)er[q].x * 8);
#pragma unroll
        for (int q = 0; q < 4; q++) {
            float wv = __int_as_float(er[q].y);   // 0 in pad region
            float2 f01 = __half22float2(*(__half2*)&rr[q].x);
            float2 f23 = __half22float2(*(__half2*)&rr[q].y);
            float2 f4x = __half22float2(*(__half2*)&rr[q].z);
            a0 += wv * f01.x; a1 += wv * f01.y;
            a2 += wv * f23.x; a3 += wv * f23.y;
            a4 += wv * f4x.x;
        }
    }
    // tail n > 32 (zero-padded to roundup8(n))
    int padEnd = beg + ((n + 7) & ~7);
    for (int e = beg + 32 + l8; e < padEnd; e += 8) {
        int2 et = g_edge[e];
        uint4 rt = *(const uint4*)(g_h2h + (size_t)et.x * 8);
        float wt = __int_as_float(et.y);
        float2 h01 = __half22float2(*(__half2*)&rt.x);
        float2 h23 = __half22float2(*(__half2*)&rt.y);
        float2 h4x = __half22float2(*(__half2*)&rt.z);
        a0 += wt * h01.x; a1 += wt * h01.y;
        a2 += wt * h23.x; a3 += wt * h23.y;
        a4 += wt * h4x.x;
    }

    // fold within the 8-lane quarter
#pragma unroll
    for (int o = 4; o > 0; o >>= 1) {
        a0 += __shfl_xor_sync(qmask, a0, o);
        a1 += __shfl_xor_sync(qmask, a1, o);
        a2 += __shfl_xor_sync(qmask, a2, o);
        a3 += __shfl_xor_sync(qmask, a3, o);
        a4 += __shfl_xor_sync(qmask, a4, o);
    }
    if (l8 < C_DIM) {
        float val = (l8 == 0) ? a0 : (l8 == 1) ? a1 : (l8 == 2) ? a2 :
                    (l8 == 3) ? a3 : a4;
        out[(size_t)node * C_DIM + l8] = val * g_dinv[node] + b2[l8];
    }
}

// ---------------- launch ----------------

extern "C" void kernel_launch(void* const* d_in, const int* in_sizes, int n_in,
                              void* d_out, int out_size) {
    const float* x   = (const float*)d_in[0];
    const int*   ei  = (const int*)d_in[1];     // JAX demotes int64 -> int32
    const float* ew  = (const float*)d_in[2];
    const float* W1  = (const float*)d_in[3];
    const float* b1  = (const float*)d_in[4];
    const float* W2  = (const float*)d_in[5];
    const float* b2  = (const float*)d_in[6];
    float* out = (float*)d_out;

    const int E = in_sizes[2];
    const int* src = ei;
    const int* dst = ei + E;

    float* x2_out = out;                            // [N, C]
    float* x1_out = out + (size_t)N_NODES * C_DIM;  // [N, H]

    const int T = 256;
    const int gE2 = ((E + 1) / 2 + T - 1) / T;                  // hist: 2 edges/thread
    const int gN2 = (N_NODES * 2 + T - 1) / T;                  // gemm1 blocks
    const int gP  = (N_NODES * (H_DIM / 4) + T - 1) / T;        // prep blocks
    const int gH  = (N_NODES * 16 + T - 1) / T;                 // half-warp/node (agg1)
    const int gQ  = (N_NODES * 8 + T - 1) / T;                  // quarter-warp/node (agg2)

    k_hist_gemm1 <<<gN2 + gE2, T>>>(src, dst, ew, E, x, W1, gN2);
    k_prep       <<<gP,        T>>>();
    k_agg1       <<<gH,        T>>>(b1, W2, x1_out);
    k_agg2       <<<gQ,        T>>>(b2, x2_out);
}